// round 16
// baseline (speedup 1.0000x reference)
#include <cuda_runtime.h>
#include <math.h>
#include <stdint.h>

#define NB   8
#define NN   256
#define NH   8
#define NLAT 32
#define SC   0.35355339059327373f

__device__ __align__(16) float g_Q   [NB*NN*64];
__device__ __align__(16) float g_Kr  [NB*NN*64];
__device__ __align__(16) float g_VtT [NB*64*NN];
__device__ __align__(16) float g_pattn[NB*NN*64];
__device__ __align__(16) float g_Kc  [NB*NN*64];
__device__ __align__(16) float g_Vc  [NB*NN*64];
__device__ __align__(16) float g_q   [NB*NLAT*64];

__device__ __forceinline__ uint32_t tf32u(float x) {
    uint32_t r; asm("cvt.rna.tf32.f32 %0, %1;" : "=r"(r) : "f"(x)); return r;
}
__device__ __forceinline__ uint32_t s2u(const void* p) {
    uint32_t a;
    asm("{ .reg .u64 t; cvta.to.shared.u64 t, %1; cvt.u32.u64 %0, t; }" : "=r"(a) : "l"(p));
    return a;
}
__device__ __forceinline__ void cpa16(uint32_t s, const void* g) {
    asm volatile("cp.async.cg.shared.global [%0], [%1], 16;" :: "r"(s), "l"(g) : "memory");
}
__device__ __forceinline__ void mma8(float* d, uint32_t a0, uint32_t a1, uint32_t a2,
                                     uint32_t a3, uint32_t b0, uint32_t b1) {
    asm("mma.sync.aligned.m16n8k8.row.col.f32.tf32.tf32.f32 "
        "{%0,%1,%2,%3}, {%4,%5,%6,%7}, {%8,%9}, {%0,%1,%2,%3};"
        : "+f"(d[0]), "+f"(d[1]), "+f"(d[2]), "+f"(d[3])
        : "r"(a0), "r"(a1), "r"(a2), "r"(a3), "r"(b0), "r"(b1));
}

// -------- K0: Q, K*SCALE, V (transposed). 4 rows/block --------
__global__ void k_qkv(const float* __restrict__ p, const float* __restrict__ wq,
                      const float* __restrict__ wk, const float* __restrict__ wv) {
    int blk = blockIdx.x, t = threadIdx.x;
    int r = t >> 6, col = t & 63;
    int bi = blk*4 + r;
    __shared__ float pr[4][64];
    pr[r][col] = p[bi*64 + col];
    __syncthreads();
    float aq = 0.f, ak = 0.f, av = 0.f;
#pragma unroll 8
    for (int c = 0; c < 64; c++) {
        float pv = pr[r][c];
        aq = fmaf(pv, wq[c*64 + col], aq);
        ak = fmaf(pv, wk[c*64 + col], ak);
        av = fmaf(pv, wv[c*64 + col], av);
    }
    int b = bi >> 8, j = bi & 255;
    g_Q[bi*64 + col] = aq;
    g_Kr[bi*64 + col] = ak * SC;
    g_VtT[(size_t)(b*64 + col)*256 + j] = av;
}

// -------- K1: cp.async double-buffered e, mma.sync TF32, fused epilogue (R15) --------
#define ECH   (128*68)
#define BQ_O  (2*ECH)
#define SS_O  (BQ_O + 32*136)
#define EDGE_SMEM ((SS_O + 8*256)*4)
__global__ void __launch_bounds__(256, 2) k_edge(const float* __restrict__ e,
                                                 const float* __restrict__ we,
                                                 const float* __restrict__ mask,
                                                 const float* __restrict__ kRW) {
    extern __shared__ float sm[];
    float* e_s = sm;
    uint2* Bq = (uint2*)(sm + BQ_O);
    float* sS = sm + SS_O;
    __shared__ float qrow[64];
    int tid = threadIdx.x, bi = blockIdx.x, b = bi >> 8, i = bi & 255;
    int w = tid >> 5, lane = tid & 31;
    int g = lane >> 2, a = lane & 3;

    const float* eg = e + (size_t)bi*16384;
    uint32_t e0 = s2u(e_s);
#pragma unroll
    for (int ch = 0; ch < 2; ch++) {
#pragma unroll
        for (int u = 0; u < 8; u++) {
            int v = tid + u*256;
            int r = v >> 4, c4 = v & 15;
            cpa16(e0 + (uint32_t)(ch*ECH + r*68 + c4*4)*4,
                  eg + (ch*128 + r)*64 + c4*4);
        }
        asm volatile("cp.async.commit_group;" ::: "memory");
    }
    if (tid < 64) qrow[tid] = g_Q[bi*64 + tid];
    for (int idx = tid; idx < 2048; idx += 256) {
        int row = idx >> 6, col2 = idx & 63;
        int k = row >> 2, aa = row & 3;
        int n2 = col2 >> 4, rem = col2 & 15;
        int gg = rem >> 1, pp = rem & 1;
        int n = n2*2 + pp, ca = k*8 + aa, cc = n*8 + gg;
        uint2 v;
        v.x = tf32u(we[ca*64 + cc]);
        v.y = tf32u(we[(ca + 4)*64 + cc]);
        Bq[row*68 + col2] = v;
    }
    int row0 = w*16 + g;
#pragma unroll
    for (int ch = 0; ch < 2; ch++) {
        if (ch == 0) asm volatile("cp.async.wait_group 1;" ::: "memory");
        else         asm volatile("cp.async.wait_group 0;" ::: "memory");
        __syncthreads();
        const float* E = e_s + ch*ECH;
        float acc[8][4];
#pragma unroll
        for (int n = 0; n < 8; n++) { acc[n][0]=0.f; acc[n][1]=0.f; acc[n][2]=0.f; acc[n][3]=0.f; }
#pragma unroll
        for (int k = 0; k < 8; k++) {
            int ca = k*8 + a;
            uint32_t h0 = tf32u(E[row0*68 + ca]);
            uint32_t h1 = tf32u(E[(row0 + 8)*68 + ca]);
            uint32_t h2 = tf32u(E[row0*68 + ca + 4]);
            uint32_t h3 = tf32u(E[(row0 + 8)*68 + ca + 4]);
            const uint2* Brow = Bq + (k*4 + a)*68 + g*2;
#pragma unroll
            for (int n2 = 0; n2 < 4; n2++) {
                uint4 bb = *(const uint4*)&Brow[n2*16];
                mma8(acc[2*n2],     h0, h1, h2, h3, bb.x, bb.y);
                mma8(acc[2*n2 + 1], h0, h1, h2, h3, bb.z, bb.w);
            }
        }
        int j0 = ch*128 + row0;
        const float2* Kr0 = (const float2*)(g_Kr + ((size_t)(b*256 + j0))*64);
        const float2* Kr1 = (const float2*)(g_Kr + ((size_t)(b*256 + j0 + 8))*64);
#pragma unroll
        for (int n = 0; n < 8; n++) {
            float2 q2 = *(const float2*)&qrow[n*8 + 2*a];
            float2 k0 = Kr0[n*4 + a];
            float2 k1 = Kr1[n*4 + a];
            float s0 = acc[n][0]*q2.x*k0.x + acc[n][1]*q2.y*k0.y;
            float s1 = acc[n][2]*q2.x*k1.x + acc[n][3]*q2.y*k1.y;
            s0 += __shfl_xor_sync(0xffffffffu, s0, 1);
            s0 += __shfl_xor_sync(0xffffffffu, s0, 2);
            s1 += __shfl_xor_sync(0xffffffffu, s1, 1);
            s1 += __shfl_xor_sync(0xffffffffu, s1, 2);
            if (a == 0) {
                sS[n*256 + j0] = s0;
                sS[n*256 + j0 + 8] = s1;
            }
        }
    }
    __syncthreads();

    int th = w, tj = lane;
    float sv[8];
#pragma unroll
    for (int jj = 0; jj < 8; jj++) sv[jj] = sS[th*256 + tj + jj*32];
    float m = sv[0];
#pragma unroll
    for (int k = 1; k < 8; k++) m = fmaxf(m, sv[k]);
#pragma unroll
    for (int off = 16; off; off >>= 1)
        m = fmaxf(m, __shfl_xor_sync(0xffffffffu, m, off));
    float mi = mask[b*256 + i];
    const float* krow = kRW + ((size_t)b*256 + i)*256;
    const float* Vb = g_VtT + (size_t)(b*64 + th*8)*256;
    float av[9] = {0,0,0,0,0,0,0,0,0};
#pragma unroll
    for (int k = 0; k < 8; k++) {
        int jx = tj + k*32;
        float wgt = __expf(sv[k] - m) * mi * mask[b*256 + jx] * krow[jx];
        av[0] += wgt;
#pragma unroll
        for (int d = 0; d < 8; d++)
            av[1 + d] = fmaf(wgt, Vb[d*256 + jx], av[1 + d]);
    }
#pragma unroll
    for (int kk = 0; kk < 9; kk++)
#pragma unroll
        for (int off = 16; off; off >>= 1)
            av[kk] += __shfl_xor_sync(0xffffffffu, av[kk], off);
    if (tj == 0) {
        float inv = 1.f / fmaxf(av[0], 1e-6f);
        float4 o1 = {av[1]*inv, av[2]*inv, av[3]*inv, av[4]*inv};
        float4 o2 = {av[5]*inv, av[6]*inv, av[7]*inv, av[8]*inv};
        float4* dst = (float4*)(g_pattn + ((size_t)(b*256 + i))*64 + th*8);
        dst[0] = o1; dst[1] = o2;
    }
}

// -------- K2: h_c + tanh proj fused with Kc/Vc projection --------
__global__ void k_hckv(const float* __restrict__ hh, const float* __restrict__ p,
                       const float* __restrict__ wo, const float* __restrict__ wkv) {
    int blk = blockIdx.x, t = threadIdx.x;
    int bi0 = blk*8;
    __shared__ float pa[8][64], hcs[8][64];
    {
        int r = t >> 6, col = t & 63;
        pa[r][col]     = g_pattn[(bi0 + r)*64 + col];
        pa[r + 4][col] = g_pattn[(bi0 + r + 4)*64 + col];
    }
    __syncthreads();
    {
        int rp = t >> 6, col = t & 63;
        float a0 = 0.f, a1 = 0.f;
#pragma unroll 8
        for (int c = 0; c < 64; c++) {
            float wv = wo[c*64 + col];
            a0 = fmaf(pa[rp][c], wv, a0);
            a1 = fmaf(pa[rp + 4][c], wv, a1);
        }
        int bi = bi0 + rp;
        hcs[rp][col]     = hh[bi*64 + col] + p[bi*64 + col] + tanhf(a0);
        hcs[rp + 4][col] = hh[(bi + 4)*64 + col] + p[(bi + 4)*64 + col] + tanhf(a1);
    }
    __syncthreads();
    {
        int o = t & 127, rq = t >> 7;
        float a[4] = {0, 0, 0, 0};
#pragma unroll 8
        for (int c = 0; c < 64; c++) {
            float wv = wkv[c*128 + o];
#pragma unroll
            for (int k = 0; k < 4; k++) a[k] = fmaf(hcs[rq + 2*k][c], wv, a[k]);
        }
#pragma unroll
        for (int k = 0; k < 4; k++) {
            int bi = bi0 + rq + 2*k;
            if (o < 64) g_Kc[bi*64 + o] = a[k]; else g_Vc[bi*64 + (o - 64)] = a[k];
        }
    }
}

// -------- K3: perceiver cross-attention --------
__global__ void k_cross(const float* __restrict__ queries, const float* __restrict__ mask,
                        const float* __restrict__ wq, const float* __restrict__ wo,
                        const float* __restrict__ bo) {
    int blk = blockIdx.x, b = blk >> 5, t = threadIdx.x;
    __shared__ __align__(16) float q2[64];
    __shared__ float sq[64];
    __shared__ float att[64];
    __shared__ float simb[8*256];
    if (t < 64) sq[t] = queries[blk*64 + t];
    __syncthreads();
    if (t < 64) {
        float a = 0.f;
#pragma unroll 8
        for (int c = 0; c < 64; c++) a = fmaf(sq[c], wq[c*64 + t], a);
        q2[t] = a;
    }
    __syncthreads();
    {
        int j = t;
        bool mk = mask[b*256 + j] > 0.5f;
        const float* Kr = g_Kc + ((size_t)(b*256 + j))*64;
#pragma unroll
        for (int h = 0; h < 8; h++) {
            float4 ka = *(const float4*)(Kr + h*8);
            float4 kb = *(const float4*)(Kr + h*8 + 4);
            float4 qa = *(const float4*)(q2 + h*8);
            float4 qb = *(const float4*)(q2 + h*8 + 4);
            float s = ka.x*qa.x + ka.y*qa.y + ka.z*qa.z + ka.w*qa.w
                    + kb.x*qb.x + kb.y*qb.y + kb.z*qb.z + kb.w*qb.w;
            s *= SC;
            if (!mk) s = -3.402823466e38f;
            simb[h*256 + j] = fminf(5.f, fmaxf(-5.f, s));
        }
    }
    __syncthreads();
    int h = t >> 5, lane = t & 31;
    {
        float sum = 0.f, o[8] = {0,0,0,0,0,0,0,0};
        for (int j = lane; j < 256; j += 32) {
            float ev = __expf(simb[h*256 + j]);
            sum += ev;
            const float4* V4 = (const float4*)(g_Vc + ((size_t)(b*256 + j))*64 + h*8);
            float4 va = V4[0], vb = V4[1];
            o[0] = fmaf(ev, va.x, o[0]); o[1] = fmaf(ev, va.y, o[1]);
            o[2] = fmaf(ev, va.z, o[2]); o[3] = fmaf(ev, va.w, o[3]);
            o[4] = fmaf(ev, vb.x, o[4]); o[5] = fmaf(ev, vb.y, o[5]);
            o[6] = fmaf(ev, vb.z, o[6]); o[7] = fmaf(ev, vb.w, o[7]);
        }
#pragma unroll
        for (int off = 16; off; off >>= 1) {
            sum += __shfl_xor_sync(0xffffffffu, sum, off);
#pragma unroll
            for (int d = 0; d < 8; d++) o[d] += __shfl_xor_sync(0xffffffffu, o[d], off);
        }
        if (lane == 0) {
            float inv = 1.f / sum;
#pragma unroll
            for (int d = 0; d < 8; d++) att[h*8 + d] = o[d]*inv;
        }
    }
    __syncthreads();
    if (t < 64) {
        float a = bo[t];
#pragma unroll 8
        for (int c = 0; c < 64; c++) a = fmaf(att[c], wo[c*64 + t], a);
        g_q[blk*64 + t] = sq[t] + a;
    }
}

// -------- shared latent-layer body: computes q_new[64] for (b, li) into qn --------
__device__ __forceinline__ void lat_body(int b, int li, int t,
                                         const float* __restrict__ wq,
                                         const float* __restrict__ wkv,
                                         const float* __restrict__ wo,
                                         const float* __restrict__ bo,
                                         float* qsb, float* Ks, float* Vs,
                                         float* q2, float* att, float* qn) {
#pragma unroll
    for (int k = 0; k < 8; k++) qsb[t + 256*k] = g_q[b*2048 + t + 256*k];
    __syncthreads();
    // K/V for ALL 32 latents (redundant per block; removes cross-block dep)
#pragma unroll
    for (int rep = 0; rep < 16; rep++) {
        int idx = t + rep*256;
        int l = idx >> 7, o = idx & 127;
        float a = 0.f;
#pragma unroll 8
        for (int c = 0; c < 64; c++) a = fmaf(qsb[l*64 + c], wkv[c*128 + o], a);
        if (o < 64) Ks[l*64 + o] = a; else Vs[l*64 + (o - 64)] = a;
    }
    if (t < 64) {
        float a = 0.f;
#pragma unroll 8
        for (int c = 0; c < 64; c++) a = fmaf(qsb[li*64 + c], wq[c*64 + t], a);
        q2[t] = a;
    }
    __syncthreads();
    // attention: warp h, lane j over 32 latents
    int h = t >> 5, j = t & 31;
    float s = 0.f;
#pragma unroll
    for (int k = 0; k < 8; k++) s = fmaf(q2[h*8 + k], Ks[j*64 + h*8 + k], s);
    s = fminf(5.f, fmaxf(-5.f, s*SC));
    float ev = __expf(s);
    float sum = ev;
#pragma unroll
    for (int off = 16; off; off >>= 1)
        sum += __shfl_xor_sync(0xffffffffu, sum, off);
    float o8[8];
#pragma unroll
    for (int d = 0; d < 8; d++) o8[d] = ev * Vs[j*64 + h*8 + d];
#pragma unroll
    for (int off = 16; off; off >>= 1)
#pragma unroll
        for (int d = 0; d < 8; d++) o8[d] += __shfl_xor_sync(0xffffffffu, o8[d], off);
    if (j == 0) {
        float inv = 1.f / sum;
#pragma unroll
        for (int d = 0; d < 8; d++) att[h*8 + d] = o8[d]*inv;
    }
    __syncthreads();
    if (t < 64) {
        float a = bo[t];
#pragma unroll 8
        for (int c = 0; c < 64; c++) a = fmaf(att[c], wo[c*64 + t], a);
        qn[t] = qsb[li*64 + t] + a;
    }
    __syncthreads();
}

// -------- K4: latent layer 1 (writes g_q) --------
__global__ void __launch_bounds__(256) k_lat1(const float* __restrict__ wq,
                                              const float* __restrict__ wkv,
                                              const float* __restrict__ wo,
                                              const float* __restrict__ bo) {
    __shared__ float qsb[2048], Ks[2048], Vs[2048], q2[64], att[64], qn[64];
    int blk = blockIdx.x, b = blk >> 5, li = blk & 31, t = threadIdx.x;
    lat_body(b, li, t, wq, wkv, wo, bo, qsb, Ks, Vs, q2, att, qn);
    if (t < 64) g_q[blk*64 + t] = qn[t];
}

// -------- K5: latent layer 2 + O_queries + LN1 + FFN + LN2 -> out --------
__global__ void __launch_bounds__(256) k_lat2f(const float* __restrict__ wq,
                                               const float* __restrict__ wkv,
                                               const float* __restrict__ wo,
                                               const float* __restrict__ bo,
                                               const float* __restrict__ oq,
                                               const float* __restrict__ g1,
                                               const float* __restrict__ b1,
                                               const float* __restrict__ w1,
                                               const float* __restrict__ w2,
                                               const float* __restrict__ g2,
                                               const float* __restrict__ b2,
                                               float* __restrict__ out) {
    __shared__ float qsb[2048], Ks[2048], Vs[2048], q2[64], att[64], qn[64];
    __shared__ float x[64], y[64], f1[128], z[64], mv[2];
    int blk = blockIdx.x, b = blk >> 5, li = blk & 31, t = threadIdx.x;
    lat_body(b, li, t, wq, wkv, wo, bo, qsb, Ks, Vs, q2, att, qn);
    // ---- final: x = qn @ oq; LN1; FFN; LN2 ----
    if (t < 64) {
        float a = 0.f;
#pragma unroll 8
        for (int c = 0; c < 64; c++) a = fmaf(qn[c], oq[c*64 + t], a);
        x[t] = a;
    }
    __syncthreads();
    if (t < 32) {
        float a = x[t], bb = x[t + 32];
        float su = a + bb, sq = a*a + bb*bb;
#pragma unroll
        for (int off = 16; off; off >>= 1) {
            su += __shfl_xor_sync(0xffffffffu, su, off);
            sq += __shfl_xor_sync(0xffffffffu, sq, off);
        }
        if (t == 0) { mv[0] = su/64.f; mv[1] = sq/64.f - (su/64.f)*(su/64.f); }
    }
    __syncthreads();
    if (t < 64)
        y[t] = (x[t] - mv[0])*rsqrtf(mv[1] + 1e-5f)*g1[t] + b1[t];
    __syncthreads();
    if (t < 128) {
        float a = 0.f;
#pragma unroll 8
        for (int c = 0; c < 64; c++) a = fmaf(y[c], w1[c*128 + t], a);
        f1[t] = fmaxf(a, 0.f);
    }
    __syncthreads();
    if (t < 64) {
        float a = 0.f;
#pragma unroll 8
        for (int c = 0; c < 128; c++) a = fmaf(f1[c], w2[c*64 + t], a);
        z[t] = y[t] + a;
    }
    __syncthreads();
    if (t < 32) {
        float a = z[t], bb = z[t + 32];
        float su = a + bb, sq = a*a + bb*bb;
#pragma unroll
        for (int off = 16; off; off >>= 1) {
            su += __shfl_xor_sync(0xffffffffu, su, off);
            sq += __shfl_xor_sync(0xffffffffu, sq, off);
        }
        if (t == 0) { mv[0] = su/64.f; mv[1] = sq/64.f - (su/64.f)*(su/64.f); }
    }
    __syncthreads();
    if (t < 64)
        out[blk*64 + t] = (z[t] - mv[0])*rsqrtf(mv[1] + 1e-5f)*g2[t] + b2[t];
}

extern "C" void kernel_launch(void* const* d_in, const int* in_sizes, int n_in,
                              void* d_out, int out_size) {
    const float* h_    = (const float*)d_in[0];
    const float* p     = (const float*)d_in[1];
    const float* e     = (const float*)d_in[2];
    const float* kRW   = (const float*)d_in[3];
    const float* qrs   = (const float*)d_in[4];
    const float* mask  = (const float*)d_in[5];
    const float* wq_p  = (const float*)d_in[6];
    const float* wk_p  = (const float*)d_in[7];
    const float* we_p  = (const float*)d_in[8];
    const float* wv_p  = (const float*)d_in[9];
    const float* wo_p  = (const float*)d_in[10];
    const float* cq_wq = (const float*)d_in[11];
    const float* cq_wkv= (const float*)d_in[12];
    const float* cq_wo = (const float*)d_in[13];
    const float* cq_bo = (const float*)d_in[14];
    const float* sa_wq = (const float*)d_in[15];
    const float* sa_wkv= (const float*)d_in[16];
    const float* sa_wo = (const float*)d_in[17];
    const float* sa_bo = (const float*)d_in[18];
    const float* oq_w  = (const float*)d_in[19];
    const float* ln1g  = (const float*)d_in[20];
    const float* ln1b  = (const float*)d_in[21];
    const float* fw1   = (const float*)d_in[22];
    const float* fw2   = (const float*)d_in[23];
    const float* ln2g  = (const float*)d_in[24];
    const float* ln2b  = (const float*)d_in[25];
    float* out = (float*)d_out;

    static int configured = 0;
    if (!configured) {
        cudaFuncSetAttribute(k_edge, cudaFuncAttributeMaxDynamicSharedMemorySize, EDGE_SMEM);
        configured = 1;
    }

    k_qkv   <<<NB*NN/4, 256>>>(p, wq_p, wk_p, wv_p);            // 1
    k_edge  <<<NB*NN, 256, EDGE_SMEM>>>(e, we_p, mask, kRW);     // 2
    k_hckv  <<<NB*NN/8, 256>>>(h_, p, wo_p, cq_wkv);             // 3
    k_cross <<<NB*NLAT, 256>>>(qrs, mask, cq_wq, cq_wo, cq_bo);  // 4 -> profiled
    k_lat1  <<<NB*NLAT, 256>>>(sa_wq, sa_wkv, sa_wo, sa_bo);
    k_lat2f <<<NB*NLAT, 256>>>(sa_wq + 4096, sa_wkv + 8192, sa_wo + 4096, sa_bo + 64,
                               oq_w, ln1g, ln1b, fw1, fw2, ln2g, ln2b, out);
}

// round 17
// speedup vs baseline: 1.3133x; 1.3133x over previous
#include <cuda_runtime.h>
#include <math.h>
#include <stdint.h>

#define NB   8
#define NN   256
#define NH   8
#define NLAT 32
#define SC   0.35355339059327373f

__device__ __align__(16) float g_Q   [NB*NN*64];
__device__ __align__(16) float g_Kr  [NB*NN*64];
__device__ __align__(16) float g_VtT [NB*64*NN];
__device__ __align__(16) float g_pattn[NB*NN*64];
__device__ __align__(16) float g_Kc  [NB*NN*64];
__device__ __align__(16) float g_Vc  [NB*NN*64];
__device__ __align__(16) float g_q   [NB*NLAT*64];
__device__ __align__(16) float g_q2  [NB*NLAT*64];
__device__ __align__(16) float g_Kl  [NB*NLAT*64];
__device__ __align__(16) float g_Vl  [NB*NLAT*64];

__device__ __forceinline__ uint32_t tf32u(float x) {
    uint32_t r; asm("cvt.rna.tf32.f32 %0, %1;" : "=r"(r) : "f"(x)); return r;
}
__device__ __forceinline__ uint32_t s2u(const void* p) {
    uint32_t a;
    asm("{ .reg .u64 t; cvta.to.shared.u64 t, %1; cvt.u32.u64 %0, t; }" : "=r"(a) : "l"(p));
    return a;
}
__device__ __forceinline__ void cpa16(uint32_t s, const void* g) {
    asm volatile("cp.async.cg.shared.global [%0], [%1], 16;" :: "r"(s), "l"(g) : "memory");
}
__device__ __forceinline__ void mma8(float* d, uint32_t a0, uint32_t a1, uint32_t a2,
                                     uint32_t a3, uint32_t b0, uint32_t b1) {
    asm("mma.sync.aligned.m16n8k8.row.col.f32.tf32.tf32.f32 "
        "{%0,%1,%2,%3}, {%4,%5,%6,%7}, {%8,%9}, {%0,%1,%2,%3};"
        : "+f"(d[0]), "+f"(d[1]), "+f"(d[2]), "+f"(d[3])
        : "r"(a0), "r"(a1), "r"(a2), "r"(a3), "r"(b0), "r"(b1));
}

// -------- per-latent projection tail (exact old k_selfqkv body, from smem qn) --------
__device__ __forceinline__ void proj_tail(int blk, int t, const float* qn,
                                          const float* __restrict__ wq,
                                          const float* __restrict__ wkv) {
    if (t < 64) {
        float a = 0.f;
#pragma unroll 8
        for (int c = 0; c < 64; c++) a = fmaf(qn[c], wq[c*64 + t], a);
        g_q2[blk*64 + t] = a;
    } else if (t < 192) {
        int o = t - 64;
        float a = 0.f;
#pragma unroll 8
        for (int c = 0; c < 64; c++) a = fmaf(qn[c], wkv[c*128 + o], a);
        if (o < 64) g_Kl[blk*64 + o] = a; else g_Vl[blk*64 + (o - 64)] = a;
    }
}

// -------- K0: Q, K*SCALE, V (transposed). 4 rows/block --------
__global__ void k_qkv(const float* __restrict__ p, const float* __restrict__ wq,
                      const float* __restrict__ wk, const float* __restrict__ wv) {
    int blk = blockIdx.x, t = threadIdx.x;
    int r = t >> 6, col = t & 63;
    int bi = blk*4 + r;
    __shared__ float pr[4][64];
    pr[r][col] = p[bi*64 + col];
    __syncthreads();
    float aq = 0.f, ak = 0.f, av = 0.f;
#pragma unroll 8
    for (int c = 0; c < 64; c++) {
        float pv = pr[r][c];
        aq = fmaf(pv, wq[c*64 + col], aq);
        ak = fmaf(pv, wk[c*64 + col], ak);
        av = fmaf(pv, wv[c*64 + col], av);
    }
    int b = bi >> 8, j = bi & 255;
    g_Q[bi*64 + col] = aq;
    g_Kr[bi*64 + col] = ak * SC;
    g_VtT[(size_t)(b*64 + col)*256 + j] = av;
}

// -------- K1: cp.async double-buffered e, mma.sync TF32, fused epilogue (R15) --------
#define ECH   (128*68)
#define BQ_O  (2*ECH)
#define SS_O  (BQ_O + 32*136)
#define EDGE_SMEM ((SS_O + 8*256)*4)
__global__ void __launch_bounds__(256, 2) k_edge(const float* __restrict__ e,
                                                 const float* __restrict__ we,
                                                 const float* __restrict__ mask,
                                                 const float* __restrict__ kRW) {
    extern __shared__ float sm[];
    float* e_s = sm;
    uint2* Bq = (uint2*)(sm + BQ_O);
    float* sS = sm + SS_O;
    __shared__ float qrow[64];
    int tid = threadIdx.x, bi = blockIdx.x, b = bi >> 8, i = bi & 255;
    int w = tid >> 5, lane = tid & 31;
    int g = lane >> 2, a = lane & 3;

    const float* eg = e + (size_t)bi*16384;
    uint32_t e0 = s2u(e_s);
#pragma unroll
    for (int ch = 0; ch < 2; ch++) {
#pragma unroll
        for (int u = 0; u < 8; u++) {
            int v = tid + u*256;
            int r = v >> 4, c4 = v & 15;
            cpa16(e0 + (uint32_t)(ch*ECH + r*68 + c4*4)*4,
                  eg + (ch*128 + r)*64 + c4*4);
        }
        asm volatile("cp.async.commit_group;" ::: "memory");
    }
    if (tid < 64) qrow[tid] = g_Q[bi*64 + tid];
    for (int idx = tid; idx < 2048; idx += 256) {
        int row = idx >> 6, col2 = idx & 63;
        int k = row >> 2, aa = row & 3;
        int n2 = col2 >> 4, rem = col2 & 15;
        int gg = rem >> 1, pp = rem & 1;
        int n = n2*2 + pp, ca = k*8 + aa, cc = n*8 + gg;
        uint2 v;
        v.x = tf32u(we[ca*64 + cc]);
        v.y = tf32u(we[(ca + 4)*64 + cc]);
        Bq[row*68 + col2] = v;
    }
    int row0 = w*16 + g;
#pragma unroll
    for (int ch = 0; ch < 2; ch++) {
        if (ch == 0) asm volatile("cp.async.wait_group 1;" ::: "memory");
        else         asm volatile("cp.async.wait_group 0;" ::: "memory");
        __syncthreads();
        const float* E = e_s + ch*ECH;
        float acc[8][4];
#pragma unroll
        for (int n = 0; n < 8; n++) { acc[n][0]=0.f; acc[n][1]=0.f; acc[n][2]=0.f; acc[n][3]=0.f; }
#pragma unroll
        for (int k = 0; k < 8; k++) {
            int ca = k*8 + a;
            uint32_t h0 = tf32u(E[row0*68 + ca]);
            uint32_t h1 = tf32u(E[(row0 + 8)*68 + ca]);
            uint32_t h2 = tf32u(E[row0*68 + ca + 4]);
            uint32_t h3 = tf32u(E[(row0 + 8)*68 + ca + 4]);
            const uint2* Brow = Bq + (k*4 + a)*68 + g*2;
#pragma unroll
            for (int n2 = 0; n2 < 4; n2++) {
                uint4 bb = *(const uint4*)&Brow[n2*16];
                mma8(acc[2*n2],     h0, h1, h2, h3, bb.x, bb.y);
                mma8(acc[2*n2 + 1], h0, h1, h2, h3, bb.z, bb.w);
            }
        }
        int j0 = ch*128 + row0;
        const float2* Kr0 = (const float2*)(g_Kr + ((size_t)(b*256 + j0))*64);
        const float2* Kr1 = (const float2*)(g_Kr + ((size_t)(b*256 + j0 + 8))*64);
#pragma unroll
        for (int n = 0; n < 8; n++) {
            float2 q2 = *(const float2*)&qrow[n*8 + 2*a];
            float2 k0 = Kr0[n*4 + a];
            float2 k1 = Kr1[n*4 + a];
            float s0 = acc[n][0]*q2.x*k0.x + acc[n][1]*q2.y*k0.y;
            float s1 = acc[n][2]*q2.x*k1.x + acc[n][3]*q2.y*k1.y;
            s0 += __shfl_xor_sync(0xffffffffu, s0, 1);
            s0 += __shfl_xor_sync(0xffffffffu, s0, 2);
            s1 += __shfl_xor_sync(0xffffffffu, s1, 1);
            s1 += __shfl_xor_sync(0xffffffffu, s1, 2);
            if (a == 0) {
                sS[n*256 + j0] = s0;
                sS[n*256 + j0 + 8] = s1;
            }
        }
    }
    __syncthreads();

    int th = w, tj = lane;
    float sv[8];
#pragma unroll
    for (int jj = 0; jj < 8; jj++) sv[jj] = sS[th*256 + tj + jj*32];
    float m = sv[0];
#pragma unroll
    for (int k = 1; k < 8; k++) m = fmaxf(m, sv[k]);
#pragma unroll
    for (int off = 16; off; off >>= 1)
        m = fmaxf(m, __shfl_xor_sync(0xffffffffu, m, off));
    float mi = mask[b*256 + i];
    const float* krow = kRW + ((size_t)b*256 + i)*256;
    const float* Vb = g_VtT + (size_t)(b*64 + th*8)*256;
    float av[9] = {0,0,0,0,0,0,0,0,0};
#pragma unroll
    for (int k = 0; k < 8; k++) {
        int jx = tj + k*32;
        float wgt = __expf(sv[k] - m) * mi * mask[b*256 + jx] * krow[jx];
        av[0] += wgt;
#pragma unroll
        for (int d = 0; d < 8; d++)
            av[1 + d] = fmaf(wgt, Vb[d*256 + jx], av[1 + d]);
    }
#pragma unroll
    for (int kk = 0; kk < 9; kk++)
#pragma unroll
        for (int off = 16; off; off >>= 1)
            av[kk] += __shfl_xor_sync(0xffffffffu, av[kk], off);
    if (tj == 0) {
        float inv = 1.f / fmaxf(av[0], 1e-6f);
        float4 o1 = {av[1]*inv, av[2]*inv, av[3]*inv, av[4]*inv};
        float4 o2 = {av[5]*inv, av[6]*inv, av[7]*inv, av[8]*inv};
        float4* dst = (float4*)(g_pattn + ((size_t)(b*256 + i))*64 + th*8);
        dst[0] = o1; dst[1] = o2;
    }
}

// -------- K2: h_c + tanh proj fused with Kc/Vc projection --------
__global__ void k_hckv(const float* __restrict__ hh, const float* __restrict__ p,
                       const float* __restrict__ wo, const float* __restrict__ wkv) {
    int blk = blockIdx.x, t = threadIdx.x;
    int bi0 = blk*8;
    __shared__ float pa[8][64], hcs[8][64];
    {
        int r = t >> 6, col = t & 63;
        pa[r][col]     = g_pattn[(bi0 + r)*64 + col];
        pa[r + 4][col] = g_pattn[(bi0 + r + 4)*64 + col];
    }
    __syncthreads();
    {
        int rp = t >> 6, col = t & 63;
        float a0 = 0.f, a1 = 0.f;
#pragma unroll 8
        for (int c = 0; c < 64; c++) {
            float wv = wo[c*64 + col];
            a0 = fmaf(pa[rp][c], wv, a0);
            a1 = fmaf(pa[rp + 4][c], wv, a1);
        }
        int bi = bi0 + rp;
        hcs[rp][col]     = hh[bi*64 + col] + p[bi*64 + col] + tanhf(a0);
        hcs[rp + 4][col] = hh[(bi + 4)*64 + col] + p[(bi + 4)*64 + col] + tanhf(a1);
    }
    __syncthreads();
    {
        int o = t & 127, rq = t >> 7;
        float a[4] = {0, 0, 0, 0};
#pragma unroll 8
        for (int c = 0; c < 64; c++) {
            float wv = wkv[c*128 + o];
#pragma unroll
            for (int k = 0; k < 4; k++) a[k] = fmaf(hcs[rq + 2*k][c], wv, a[k]);
        }
#pragma unroll
        for (int k = 0; k < 4; k++) {
            int bi = bi0 + rq + 2*k;
            if (o < 64) g_Kc[bi*64 + o] = a[k]; else g_Vc[bi*64 + (o - 64)] = a[k];
        }
    }
}

// -------- K3: perceiver cross-attention + layer-0 projection tail --------
__global__ void k_crossp(const float* __restrict__ queries, const float* __restrict__ mask,
                         const float* __restrict__ wq, const float* __restrict__ wo,
                         const float* __restrict__ bo,
                         const float* __restrict__ l_wq, const float* __restrict__ l_wkv) {
    int blk = blockIdx.x, b = blk >> 5, t = threadIdx.x;
    __shared__ __align__(16) float q2[64];
    __shared__ float sq[64];
    __shared__ float att[64];
    __shared__ float qn[64];
    __shared__ float simb[8*256];
    if (t < 64) sq[t] = queries[blk*64 + t];
    __syncthreads();
    if (t < 64) {
        float a = 0.f;
#pragma unroll 8
        for (int c = 0; c < 64; c++) a = fmaf(sq[c], wq[c*64 + t], a);
        q2[t] = a;
    }
    __syncthreads();
    {
        int j = t;
        bool mk = mask[b*256 + j] > 0.5f;
        const float* Kr = g_Kc + ((size_t)(b*256 + j))*64;
#pragma unroll
        for (int h = 0; h < 8; h++) {
            float4 ka = *(const float4*)(Kr + h*8);
            float4 kb = *(const float4*)(Kr + h*8 + 4);
            float4 qa = *(const float4*)(q2 + h*8);
            float4 qb = *(const float4*)(q2 + h*8 + 4);
            float s = ka.x*qa.x + ka.y*qa.y + ka.z*qa.z + ka.w*qa.w
                    + kb.x*qb.x + kb.y*qb.y + kb.z*qb.z + kb.w*qb.w;
            s *= SC;
            if (!mk) s = -3.402823466e38f;
            simb[h*256 + j] = fminf(5.f, fmaxf(-5.f, s));
        }
    }
    __syncthreads();
    int h = t >> 5, lane = t & 31;
    {
        float sum = 0.f, o[8] = {0,0,0,0,0,0,0,0};
        for (int j = lane; j < 256; j += 32) {
            float ev = __expf(simb[h*256 + j]);
            sum += ev;
            const float4* V4 = (const float4*)(g_Vc + ((size_t)(b*256 + j))*64 + h*8);
            float4 va = V4[0], vb = V4[1];
            o[0] = fmaf(ev, va.x, o[0]); o[1] = fmaf(ev, va.y, o[1]);
            o[2] = fmaf(ev, va.z, o[2]); o[3] = fmaf(ev, va.w, o[3]);
            o[4] = fmaf(ev, vb.x, o[4]); o[5] = fmaf(ev, vb.y, o[5]);
            o[6] = fmaf(ev, vb.z, o[6]); o[7] = fmaf(ev, vb.w, o[7]);
        }
#pragma unroll
        for (int off = 16; off; off >>= 1) {
            sum += __shfl_xor_sync(0xffffffffu, sum, off);
#pragma unroll
            for (int d = 0; d < 8; d++) o[d] += __shfl_xor_sync(0xffffffffu, o[d], off);
        }
        if (lane == 0) {
            float inv = 1.f / sum;
#pragma unroll
            for (int d = 0; d < 8; d++) att[h*8 + d] = o[d]*inv;
        }
    }
    __syncthreads();
    if (t < 64) {
        float a = bo[t];
#pragma unroll 8
        for (int c = 0; c < 64; c++) a = fmaf(att[c], wo[c*64 + t], a);
        float v = sq[t] + a;
        g_q[blk*64 + t] = v;
        qn[t] = v;
    }
    __syncthreads();
    proj_tail(blk, t, qn, l_wq, l_wkv);
}

// -------- shared self-attn body: qn = g_q[blk] + attn-out, also writes g_q --------
__device__ __forceinline__ void self_body(int blk, int b, int t,
                                          const float* __restrict__ wo,
                                          const float* __restrict__ bo,
                                          float* Ks, float* Vs, float* q2r,
                                          float* att, float* qn) {
    for (int idx = t; idx < NLAT*64; idx += 256) {
        Ks[idx] = g_Kl[b*NLAT*64 + idx];
        Vs[idx] = g_Vl[b*NLAT*64 + idx];
    }
    if (t < 64) q2r[t] = g_q2[blk*64 + t];
    __syncthreads();
    int h = t >> 5, j = t & 31;
    float s = 0.f;
#pragma unroll
    for (int k = 0; k < 8; k++) s = fmaf(q2r[h*8 + k], Ks[j*64 + h*8 + k], s);
    s = fminf(5.f, fmaxf(-5.f, s*SC));
    float ev = __expf(s);
    float sum = ev;
#pragma unroll
    for (int off = 16; off; off >>= 1)
        sum += __shfl_xor_sync(0xffffffffu, sum, off);
    float o[8];
#pragma unroll
    for (int d = 0; d < 8; d++) o[d] = ev * Vs[j*64 + h*8 + d];
#pragma unroll
    for (int off = 16; off; off >>= 1)
#pragma unroll
        for (int d = 0; d < 8; d++) o[d] += __shfl_xor_sync(0xffffffffu, o[d], off);
    if (j == 0) {
        float inv = 1.f / sum;
#pragma unroll
        for (int d = 0; d < 8; d++) att[h*8 + d] = o[d]*inv;
    }
    __syncthreads();
    if (t < 64) {
        float a = bo[t];
#pragma unroll 8
        for (int c = 0; c < 64; c++) a = fmaf(att[c], wo[c*64 + t], a);
        float v = g_q[blk*64 + t] + a;
        g_q[blk*64 + t] = v;
        qn[t] = v;
    }
    __syncthreads();
}

// -------- K4: latent self-attn layer 0 + layer-1 projection tail --------
__global__ void __launch_bounds__(256) k_selfp(const float* __restrict__ wo,
                                               const float* __restrict__ bo,
                                               const float* __restrict__ l_wq,
                                               const float* __restrict__ l_wkv) {
    __shared__ float Ks[NLAT*64], Vs[NLAT*64], q2r[64], att[64], qn[64];
    int blk = blockIdx.x, b = blk >> 5, t = threadIdx.x;
    self_body(blk, b, t, wo, bo, Ks, Vs, q2r, att, qn);
    proj_tail(blk, t, qn, l_wq, l_wkv);
}

// -------- K5: latent self-attn layer 1 + O_queries + LN1 + FFN + LN2 -> out --------
__global__ void __launch_bounds__(256) k_selff(const float* __restrict__ wo,
                                               const float* __restrict__ bo,
                                               const float* __restrict__ oq,
                                               const float* __restrict__ g1,
                                               const float* __restrict__ b1,
                                               const float* __restrict__ w1,
                                               const float* __restrict__ w2,
                                               const float* __restrict__ g2,
                                               const float* __restrict__ b2,
                                               float* __restrict__ out) {
    __shared__ float Ks[NLAT*64], Vs[NLAT*64], q2r[64], att[64], qn[64];
    __shared__ float x[64], y[64], f1[128], z[64], mv[2];
    int blk = blockIdx.x, b = blk >> 5, t = threadIdx.x;
    self_body(blk, b, t, wo, bo, Ks, Vs, q2r, att, qn);
    if (t < 64) {
        float a = 0.f;
#pragma unroll 8
        for (int c = 0; c < 64; c++) a = fmaf(qn[c], oq[c*64 + t], a);
        x[t] = a;
    }
    __syncthreads();
    if (t < 32) {
        float a = x[t], bb = x[t + 32];
        float su = a + bb, sq = a*a + bb*bb;
#pragma unroll
        for (int off = 16; off; off >>= 1) {
            su += __shfl_xor_sync(0xffffffffu, su, off);
            sq += __shfl_xor_sync(0xffffffffu, sq, off);
        }
        if (t == 0) { mv[0] = su/64.f; mv[1] = sq/64.f - (su/64.f)*(su/64.f); }
    }
    __syncthreads();
    if (t < 64)
        y[t] = (x[t] - mv[0])*rsqrtf(mv[1] + 1e-5f)*g1[t] + b1[t];
    __syncthreads();
    if (t < 128) {
        float a = 0.f;
#pragma unroll 8
        for (int c = 0; c < 64; c++) a = fmaf(y[c], w1[c*128 + t], a);
        f1[t] = fmaxf(a, 0.f);
    }
    __syncthreads();
    if (t < 64) {
        float a = 0.f;
#pragma unroll 8
        for (int c = 0; c < 128; c++) a = fmaf(f1[c], w2[c*64 + t], a);
        z[t] = y[t] + a;
    }
    __syncthreads();
    if (t < 32) {
        float a = z[t], bb = z[t + 32];
        float su = a + bb, sq = a*a + bb*bb;
#pragma unroll
        for (int off = 16; off; off >>= 1) {
            su += __shfl_xor_sync(0xffffffffu, su, off);
            sq += __shfl_xor_sync(0xffffffffu, sq, off);
        }
        if (t == 0) { mv[0] = su/64.f; mv[1] = sq/64.f - (su/64.f)*(su/64.f); }
    }
    __syncthreads();
    if (t < 64)
        out[blk*64 + t] = (z[t] - mv[0])*rsqrtf(mv[1] + 1e-5f)*g2[t] + b2[t];
}

extern "C" void kernel_launch(void* const* d_in, const int* in_sizes, int n_in,
                              void* d_out, int out_size) {
    const float* h_    = (const float*)d_in[0];
    const float* p     = (const float*)d_in[1];
    const float* e     = (const float*)d_in[2];
    const float* kRW   = (const float*)d_in[3];
    const float* qrs   = (const float*)d_in[4];
    const float* mask  = (const float*)d_in[5];
    const float* wq_p  = (const float*)d_in[6];
    const float* wk_p  = (const float*)d_in[7];
    const float* we_p  = (const float*)d_in[8];
    const float* wv_p  = (const float*)d_in[9];
    const float* wo_p  = (const float*)d_in[10];
    const float* cq_wq = (const float*)d_in[11];
    const float* cq_wkv= (const float*)d_in[12];
    const float* cq_wo = (const float*)d_in[13];
    const float* cq_bo = (const float*)d_in[14];
    const float* sa_wq = (const float*)d_in[15];
    const float* sa_wkv= (const float*)d_in[16];
    const float* sa_wo = (const float*)d_in[17];
    const float* sa_bo = (const float*)d_in[18];
    const float* oq_w  = (const float*)d_in[19];
    const float* ln1g  = (const float*)d_in[20];
    const float* ln1b  = (const float*)d_in[21];
    const float* fw1   = (const float*)d_in[22];
    const float* fw2   = (const float*)d_in[23];
    const float* ln2g  = (const float*)d_in[24];
    const float* ln2b  = (const float*)d_in[25];
    float* out = (float*)d_out;

    static int configured = 0;
    if (!configured) {
        cudaFuncSetAttribute(k_edge, cudaFuncAttributeMaxDynamicSharedMemorySize, EDGE_SMEM);
        configured = 1;
    }

    k_qkv   <<<NB*NN/4, 256>>>(p, wq_p, wk_p, wv_p);              // 1
    k_edge  <<<NB*NN, 256, EDGE_SMEM>>>(e, we_p, mask, kRW);       // 2
    k_hckv  <<<NB*NN/8, 256>>>(h_, p, wo_p, cq_wkv);               // 3
    k_crossp<<<NB*NLAT, 256>>>(qrs, mask, cq_wq, cq_wo, cq_bo,     // 4 -> profiled
                               sa_wq, sa_wkv);
    k_selfp <<<NB*NLAT, 256>>>(sa_wo, sa_bo, sa_wq + 4096, sa_wkv + 8192);
    k_selff <<<NB*NLAT, 256>>>(sa_wo + 4096, sa_bo + 64,
                               oq_w, ln1g, ln1b, fw1, fw2, ln2g, ln2b, out);
}